// round 12
// baseline (speedup 1.0000x reference)
#include <cuda_runtime.h>
#include <cuda_fp16.h>
#include <math.h>
#include <stdint.h>

#define NITEM   50000
#define NNODES  100000
#define NSEG    200000      // 2 * NNODES (row, col-half) segments
#define EMB     512
#define BATCH   4096
#define NSLOT   8192
#define NNZMAX  3200000
#define NCH     48          // 1536 / 32 K-chunks
#define STRB    80          // smem row stride bytes (40 halves)
#define STAGE_SZ 30720      // A 10KB + B 20KB (fp16)
#define GEMM_SMEM 62464     // 2 stages + 1KB bias
#define SCANB   782

// ---------------- static device scratch ----------------
__device__ float g_egoA[51200000];   // ego0 fp32, preserved
__device__ float g_egoB[51200000];   // layer-1 activations fp32
__device__ float g_egoC[51200000];   // layer-2 activations fp32
__device__ float g_ego3[4194304];    // 8192 x 512
__device__ __half g_a16[51200000];   // fp16 ego0 (gather source, layer 0)
__device__ __half g_x16[51200000];   // fp16 current-layer ego (gather source)
__device__ __half g_s16[51200000];   // side (fp16, GEMM A seg0)
__device__ __half g_d16[51200000];   // edis (fp16, GEMM A seg1; fixed after L0)
__device__ __half g_h16[51200000];   // h    (fp16, GEMM A seg2)
__device__ int   g_rowptr[NSEG + 1];
__device__ int   g_ofs[NSEG];
__device__ int   g_bsum[1024];
__device__ int   g_boff[1024];
__device__ int   g_scol[NNZMAX];
__device__ float g_sval[NNZMAX];
__device__ __half g_wt16[3 * 512 * 1536];  // W^T fp16, [layer][N][K]

__device__ __forceinline__ uint32_t smem_u32(const void* p) {
    uint32_t a;
    asm("{ .reg .u64 t; cvta.to.shared.u64 t, %1; cvt.u32.u64 %0, t; }" : "=r"(a) : "l"(p));
    return a;
}
#define LDSM4(r0,r1,r2,r3,addr) \
    asm volatile("ldmatrix.sync.aligned.m8n8.x4.shared.b16 {%0,%1,%2,%3}, [%4];" \
                 : "=r"(r0),"=r"(r1),"=r"(r2),"=r"(r3) : "r"(addr))
#define MMAF16(d,a,b) \
    asm volatile("mma.sync.aligned.m16n8k16.row.col.f32.f16.f16.f32 " \
                 "{%0,%1,%2,%3}, {%4,%5,%6,%7}, {%8,%9}, {%0,%1,%2,%3};" \
                 : "+f"(d[0]),"+f"(d[1]),"+f"(d[2]),"+f"(d[3]) \
                 : "r"(a[0]),"r"(a[1]),"r"(a[2]),"r"(a[3]), "r"(b[0]),"r"(b[1]))
#define CP16(smaddr, gptr) \
    asm volatile("cp.async.ca.shared.global [%0], [%1], 16;" :: "r"(smaddr), "l"(gptr) : "memory")
#define CP_COMMIT() asm volatile("cp.async.commit_group;" ::: "memory")
#define CP_WAIT0()  asm volatile("cp.async.wait_group 0;" ::: "memory")

__device__ __forceinline__ uint32_t packh2(float a, float b) {
    __half2 p = __floats2half2_rn(a, b);
    return *reinterpret_cast<uint32_t*>(&p);
}
__device__ __forceinline__ uint4 pack8(const float* f) {
    uint4 u;
    u.x = packh2(f[0], f[1]); u.y = packh2(f[2], f[3]);
    u.z = packh2(f[4], f[5]); u.w = packh2(f[6], f[7]);
    return u;
}
__device__ __forceinline__ void unpack8(uint4 u, float* f) {
    const __half2* h = (const __half2*)&u;
    #pragma unroll
    for (int j = 0; j < 4; j++) {
        float2 t = __half22float2(h[j]);
        f[2 * j] = t.x; f[2 * j + 1] = t.y;
    }
}

// ---------------- init: ego0 = [vision;text] (fp32 + fp16 copy) ----------------
__global__ void k_init(const float* __restrict__ vis, const float* __restrict__ txt)
{
    size_t i = (size_t)blockIdx.x * blockDim.x + threadIdx.x;
    size_t half = (size_t)NITEM * EMB / 4;
    if (i >= half) return;
    float4 v = ((const float4*)vis)[i];
    float4 t = ((const float4*)txt)[i];
    ((float4*)g_egoA)[i]        = v;
    ((float4*)g_egoA)[half + i] = t;
    __half2 hv[2] = { __floats2half2_rn(v.x, v.y), __floats2half2_rn(v.z, v.w) };
    __half2 ht[2] = { __floats2half2_rn(t.x, t.y), __floats2half2_rn(t.z, t.w) };
    *(uint2*)(g_a16 + 4 * i)          = *(uint2*)hv;
    *(uint2*)(g_a16 + 4 * (half + i)) = *(uint2*)ht;
}

__global__ void k_zero2()
{
    int i = blockIdx.x * blockDim.x + threadIdx.x;
    if (i < NSEG) g_ofs[i] = 0;
}

// ---------------- CSR build: key = 2*row + (col >= NITEM) ----------------
__global__ void k_hist(const int* __restrict__ er, const int* __restrict__ ec, int nnz)
{
    int i = blockIdx.x * blockDim.x + threadIdx.x;
    int stride = gridDim.x * blockDim.x;
    for (int e = i; e < nnz; e += stride)
        atomicAdd(&g_ofs[2 * er[e] + (ec[e] >= NITEM)], 1);
}

__global__ void k_scan1()
{
    __shared__ int sm[256];
    int t = threadIdx.x;
    int idx = blockIdx.x * 256 + t;
    int v = (idx < NSEG) ? g_ofs[idx] : 0;
    sm[t] = v;
    __syncthreads();
    #pragma unroll
    for (int off = 128; off; off >>= 1) {
        if (t < off) sm[t] += sm[t + off];
        __syncthreads();
    }
    if (t == 0) g_bsum[blockIdx.x] = sm[0];
}

__global__ void k_scan2()
{
    __shared__ int sm[1024];
    int t = threadIdx.x;
    int v = (t < SCANB) ? g_bsum[t] : 0;
    sm[t] = v;
    __syncthreads();
    #pragma unroll
    for (int off = 1; off < 1024; off <<= 1) {
        int add = (t >= off) ? sm[t - off] : 0;
        __syncthreads();
        sm[t] += add;
        __syncthreads();
    }
    if (t < SCANB) g_boff[t] = sm[t] - v;
    if (t == 1023) g_rowptr[NSEG] = sm[1023];
}

__global__ void k_scan3()
{
    __shared__ int sm[256];
    int t = threadIdx.x;
    int idx = blockIdx.x * 256 + t;
    int v = (idx < NSEG) ? g_ofs[idx] : 0;
    sm[t] = v;
    __syncthreads();
    #pragma unroll
    for (int off = 1; off < 256; off <<= 1) {
        int add = (t >= off) ? sm[t - off] : 0;
        __syncthreads();
        sm[t] += add;
        __syncthreads();
    }
    int ex = sm[t] - v + g_boff[blockIdx.x];
    if (idx < NSEG) { g_rowptr[idx] = ex; g_ofs[idx] = ex; }
}

__global__ void k_scatter(const int* __restrict__ er, const int* __restrict__ ec,
                          const float* __restrict__ ev, int nnz)
{
    int i = blockIdx.x * blockDim.x + threadIdx.x;
    int stride = gridDim.x * blockDim.x;
    for (int e = i; e < nnz; e += stride) {
        int c = ec[e];
        int pos = atomicAdd(&g_ofs[2 * er[e] + (c >= NITEM)], 1);
        g_scol[pos] = c;
        g_sval[pos] = ev[e];
    }
}

// ---------------- SpMM helpers ----------------
__device__ __forceinline__ void fma8(float* f, uint4 u, float v)
{
    const __half2* h = (const __half2*)&u;
    #pragma unroll
    for (int j = 0; j < 4; j++) {
        float2 t = __half22float2(h[j]);
        f[2 * j]     = fmaf(t.x, v, f[2 * j]);
        f[2 * j + 1] = fmaf(t.y, v, f[2 * j + 1]);
    }
}

__device__ __forceinline__ void accum16(const __half* __restrict__ x, int s, int e,
                                        int lane, float* f)
{
    int i = s;
    for (; i + 1 < e; i += 2) {
        int   c0 = g_scol[i],  c1 = g_scol[i + 1];
        float v0 = g_sval[i],  v1 = g_sval[i + 1];
        const uint4* xa = (const uint4*)(x + (size_t)c0 * EMB);
        const uint4* xb = (const uint4*)(x + (size_t)c1 * EMB);
        uint4 a0 = __ldcg(&xa[lane]), a1 = __ldcg(&xa[lane + 32]);
        uint4 b0 = __ldcg(&xb[lane]), b1 = __ldcg(&xb[lane + 32]);
        fma8(f,     a0, v0); fma8(f + 8, a1, v0);
        fma8(f,     b0, v1); fma8(f + 8, b1, v1);
    }
    if (i < e) {
        int   c0 = g_scol[i];
        float v0 = g_sval[i];
        const uint4* xa = (const uint4*)(x + (size_t)c0 * EMB);
        uint4 a0 = __ldcg(&xa[lane]), a1 = __ldcg(&xa[lane + 32]);
        fma8(f, a0, v0); fma8(f + 8, a1, v0);
    }
}

// side += v*x[c]; edis += v*x[c+adj]  (adj = +N for seg0 edges, -N for seg1)
__device__ __forceinline__ void accum16_dual(const __half* __restrict__ x, int s, int e,
                                             int adj, int lane, float* fs, float* fd)
{
    for (int i = s; i < e; i++) {
        int   c = g_scol[i];
        float v = g_sval[i];
        const uint4* xa = (const uint4*)(x + (size_t)c * EMB);
        const uint4* xo = (const uint4*)(x + (size_t)(c + adj) * EMB);
        uint4 a0 = __ldcg(&xa[lane]), a1 = __ldcg(&xa[lane + 32]);
        uint4 o0 = __ldcg(&xo[lane]), o1 = __ldcg(&xo[lane + 32]);
        fma8(fs,     a0, v); fma8(fs + 8, a1, v);
        fma8(fd,     o0, v); fma8(fd + 8, o1, v);
    }
}

// ---------------- SpMM full: warp per row, single pass, h fused, fp16 out ----------------
__global__ void k_spmm_full(int srcSel, int doEdis)
{
    const __half* x16 = srcSel ? g_x16 : g_a16;
    const float* egoF = srcSel ? g_egoB : g_egoA;
    int lane = threadIdx.x & 31;
    int warp = (int)((blockIdx.x * blockDim.x + threadIdx.x) >> 5);
    int nw   = (int)((gridDim.x * blockDim.x) >> 5);

    int fi[4] = { 2 * lane, 2 * lane + 1, 2 * lane + 64, 2 * lane + 65 };

    for (int row = warp; row < NNODES; row += nw) {
        int b0 = g_rowptr[2 * row], b1 = g_rowptr[2 * row + 1], b2 = g_rowptr[2 * row + 2];
        float sacc[16], dacc[16];
        #pragma unroll
        for (int q = 0; q < 16; q++) { sacc[q] = 0.f; dacc[q] = 0.f; }

        if (doEdis) {
            accum16_dual(x16, b0, b1, +NITEM, lane, sacc, dacc);  // seg0: c < N
            accum16_dual(x16, b1, b2, -NITEM, lane, sacc, dacc);  // seg1: c >= N
        } else {
            accum16(x16, b0, b2, lane, sacc);
            uint4* dd = (uint4*)(g_d16 + (size_t)row * EMB);
            unpack8(__ldcg(&dd[lane]),      dacc);
            unpack8(__ldcg(&dd[lane + 32]), dacc + 8);
        }

        int rowo = (row < NITEM) ? row + NITEM : row - NITEM;
        const float4* eg = (const float4*)(egoF + (size_t)row * EMB);
        const float4* og = (const float4*)(g_egoA + (size_t)rowo * EMB);

        float hv[16];
        #pragma unroll
        for (int q = 0; q < 4; q++) {
            float4 e = eg[fi[q]];
            float4 o = og[fi[q]];
            hv[4 * q + 0] = fmaf(e.x, sacc[4 * q + 0], o.x * dacc[4 * q + 0]);
            hv[4 * q + 1] = fmaf(e.y, sacc[4 * q + 1], o.y * dacc[4 * q + 1]);
            hv[4 * q + 2] = fmaf(e.z, sacc[4 * q + 2], o.z * dacc[4 * q + 2]);
            hv[4 * q + 3] = fmaf(e.w, sacc[4 * q + 3], o.w * dacc[4 * q + 3]);
        }

        uint4* so = (uint4*)(g_s16 + (size_t)row * EMB);
        uint4* ho = (uint4*)(g_h16 + (size_t)row * EMB);
        __stcs(&so[lane],      pack8(sacc));
        __stcs(&so[lane + 32], pack8(sacc + 8));
        __stcs(&ho[lane],      pack8(hv));
        __stcs(&ho[lane + 32], pack8(hv + 8));
        if (doEdis) {
            uint4* de = (uint4*)(g_d16 + (size_t)row * EMB);
            __stcs(&de[lane],      pack8(dacc));
            __stcs(&de[lane + 32], pack8(dacc + 8));
        }
    }
}

// ---------------- SpMM slots: warp per gathered slot (layer 2), h fused ----------------
__global__ void k_spmm_slots(const int* __restrict__ items)
{
    int lane = threadIdx.x & 31;
    int slot = (int)((blockIdx.x * blockDim.x + threadIdx.x) >> 5);
    if (slot >= NSLOT) return;
    int row = (slot < BATCH) ? items[slot] : (items[slot - BATCH] + NITEM);
    int b0 = g_rowptr[2 * row], b2 = g_rowptr[2 * row + 2];
    float sacc[16], dacc[16];
    #pragma unroll
    for (int q = 0; q < 16; q++) { sacc[q] = 0.f; dacc[q] = 0.f; }
    accum16(g_x16, b0, b2, lane, sacc);
    uint4* dd = (uint4*)(g_d16 + (size_t)row * EMB);
    unpack8(__ldcg(&dd[lane]),      dacc);
    unpack8(__ldcg(&dd[lane + 32]), dacc + 8);

    int fi[4] = { 2 * lane, 2 * lane + 1, 2 * lane + 64, 2 * lane + 65 };
    int rowo = (row < NITEM) ? row + NITEM : row - NITEM;
    const float4* eg = (const float4*)(g_egoC + (size_t)row * EMB);
    const float4* og = (const float4*)(g_egoA + (size_t)rowo * EMB);
    float hv[16];
    #pragma unroll
    for (int q = 0; q < 4; q++) {
        float4 e = eg[fi[q]];
        float4 o = og[fi[q]];
        hv[4 * q + 0] = fmaf(e.x, sacc[4 * q + 0], o.x * dacc[4 * q + 0]);
        hv[4 * q + 1] = fmaf(e.y, sacc[4 * q + 1], o.y * dacc[4 * q + 1]);
        hv[4 * q + 2] = fmaf(e.z, sacc[4 * q + 2], o.z * dacc[4 * q + 2]);
        hv[4 * q + 3] = fmaf(e.w, sacc[4 * q + 3], o.w * dacc[4 * q + 3]);
    }
    uint4* so = (uint4*)(g_s16 + (size_t)row * EMB);
    uint4* ho = (uint4*)(g_h16 + (size_t)row * EMB);
    so[lane]      = pack8(sacc);
    so[lane + 32] = pack8(sacc + 8);
    ho[lane]      = pack8(hv);
    ho[lane + 32] = pack8(hv + 8);
}

// ---------------- weight transpose + fp16 convert ----------------
__global__ void k_wtconv(const float* __restrict__ Wgc, const float* __restrict__ Wgc2,
                         const float* __restrict__ Wbi, int layer)
{
    __shared__ float t[32][33];
    int kb = blockIdx.x * 32;
    int nb = blockIdx.y * 32;
    int tx = threadIdx.x & 31, ty = threadIdx.x >> 5;
    int seg = kb >> 9, kloc = kb & 511;
    const float* W = (seg == 0) ? Wgc : (seg == 1) ? Wgc2 : Wbi;
    size_t lbase = (size_t)layer * 512 * 1536;
    #pragma unroll
    for (int j = 0; j < 4; j++)
        t[ty + 8 * j][tx] = W[(size_t)(kloc + ty + 8 * j) * 512 + nb + tx];
    __syncthreads();
    #pragma unroll
    for (int j = 0; j < 4; j++) {
        int n = nb + ty + 8 * j;
        g_wt16[lbase + (size_t)n * 1536 + kb + tx] = __float2half_rn(t[tx][ty + 8 * j]);
    }
}

// ---------------- mma.sync fp16 GEMM, 128x256, all-cp.async ----------------
// A = [s16 | d16 | h16]; outSel: 0=egoB 1=egoC 2=ego3
__global__ void __launch_bounds__(512)
k_gemm(int outSel, int layer,
       const float* __restrict__ bgc, const float* __restrict__ bgc2,
       const float* __restrict__ bbi,
       int M, const int* __restrict__ items)
{
    extern __shared__ __align__(16) char smbuf[];
    const uint32_t OA = 0, OB = 10240;
    float* biasP = (float*)(smbuf + 2 * STAGE_SZ);
    uint32_t smb = smem_u32(smbuf);

    int tid = threadIdx.x;
    int wid = tid >> 5, lid = tid & 31;
    int col0 = blockIdx.x * 256;
    int row0 = blockIdx.y * 128;
    int wM = wid >> 2, wN = wid & 3;

    if (tid < 256) {
        int c = col0 + tid;
        biasP[tid] = bgc[c] + bgc2[c] + bbi[c];
    }

    float* Cout = (outSel == 0) ? g_egoB : (outSel == 1) ? g_egoC : g_ego3;
    const __half* wt = g_wt16 + (size_t)layer * 512 * 1536;

    // A-load: thread -> row mA = tid>>2, 8 halves at kq8 = (tid&3)*8
    int mA = tid >> 2;
    int kq8 = (tid & 3) * 8;
    int node;
    {
        int g0 = row0 + mA;
        int s0 = (g0 < M) ? g0 : (M - 1);
        node = items ? ((s0 < BATCH) ? items[s0] : (items[s0 - BATCH] + NITEM)) : s0;
    }
    int nB = tid >> 1, kqB = (tid & 1) * 16;

    float acc[2][8][4];
    #pragma unroll
    for (int mt = 0; mt < 2; mt++)
        #pragma unroll
        for (int nt = 0; nt < 8; nt++)
            #pragma unroll
            for (int q = 0; q < 4; q++) acc[mt][nt][q] = 0.f;

    auto cpasyncA = [&](int c) {
        uint32_t base = smb + (c & 1) * STAGE_SZ;
        int seg = c >> 4;
        int kloc = (c & 15) * 32;
        const __half* src = (seg == 0) ? g_s16 : (seg == 1) ? g_d16 : g_h16;
        const char* gp = (const char*)(src + (size_t)node * EMB + kloc + kq8);
        CP16(base + OA + mA * STRB + (tid & 3) * 16, gp);
    };
    auto cpasyncB = [&](int c) {
        uint32_t base = smb + (c & 1) * STAGE_SZ;
        const char* gw = (const char*)(wt + (size_t)(col0 + nB) * 1536 + c * 32 + kqB);
        uint32_t bd = base + OB + nB * STRB + kqB * 2;
        CP16(bd, gw);
        CP16(bd + 16, gw + 16);
    };

    uint32_t aOff = (uint32_t)((wM * 32 + (lid & 15)) * STRB + (lid >> 4) * 16);
    uint32_t bOff[4];
    #pragma unroll
    for (int p = 0; p < 4; p++)
        bOff[p] = (uint32_t)((wN * 64 + p * 16 + (lid & 7) + ((lid >> 4) << 3)) * STRB + (((lid >> 3) & 1) << 4));

    cpasyncA(0);
    cpasyncB(0);
    CP_COMMIT();
    CP_WAIT0();
    __syncthreads();

    for (int c = 0; c < NCH; c++) {
        if (c + 1 < NCH) { cpasyncA(c + 1); cpasyncB(c + 1); CP_COMMIT(); }
        uint32_t sb = smb + (c & 1) * STAGE_SZ;
        #pragma unroll
        for (int kk = 0; kk < 2; kk++) {
            uint32_t ko = kk * 32;
            uint32_t ah[2][4];
            LDSM4(ah[0][0], ah[0][1], ah[0][2], ah[0][3], sb + OA + aOff + ko);
            LDSM4(ah[1][0], ah[1][1], ah[1][2], ah[1][3], sb + OA + aOff + 16 * STRB + ko);
            #pragma unroll
            for (int p = 0; p < 4; p++) {
                uint32_t b4[4];
                LDSM4(b4[0], b4[1], b4[2], b4[3], sb + OB + bOff[p] + ko);
                #pragma unroll
                for (int mt = 0; mt < 2; mt++) {
                    MMAF16(acc[mt][2 * p],     ah[mt], (b4 + 0));
                    MMAF16(acc[mt][2 * p + 1], ah[mt], (b4 + 2));
                }
            }
        }
        if (c + 1 < NCH) {
            CP_WAIT0();
            __syncthreads();
        }
    }

    // ---- epilogue: bias + leaky_relu (fp32 out + fp16 gather copy) ----
    int rA = lid >> 2;
    int cA = (lid & 3) * 2;
    #pragma unroll
    for (int mt = 0; mt < 2; mt++) {
        #pragma unroll
        for (int half = 0; half < 2; half++) {
            int gr = row0 + wM * 32 + mt * 16 + rA + half * 8;
            if (gr < M) {
                float* cp = Cout + (size_t)gr * EMB + col0 + wN * 64;
                __half* hp = g_x16 + (size_t)gr * EMB + col0 + wN * 64;
                #pragma unroll
                for (int nt = 0; nt < 8; nt++) {
                    int cc = nt * 8 + cA;
                    float x0 = acc[mt][nt][half * 2 + 0] + biasP[wN * 64 + cc];
                    float x1 = acc[mt][nt][half * 2 + 1] + biasP[wN * 64 + cc + 1];
                    float2 o;
                    o.x = (x0 > 0.f) ? x0 : 0.2f * x0;
                    o.y = (x1 > 0.f) ? x1 : 0.2f * x1;
                    *(float2*)(cp + cc) = o;
                    if (outSel < 2)
                        *(__half2*)(hp + cc) = __floats2half2_rn(o.x, o.y);
                }
            }
        }
    }
}

// ---------------- out[slot] = ego0[node]  (acc init) ----------------
__global__ void k_out_init(const int* __restrict__ items, float* __restrict__ out)
{
    int slot = blockIdx.x;
    int node = (slot < BATCH) ? items[slot] : (items[slot - BATCH] + NITEM);
    int t = threadIdx.x;
    float4 x = *(const float4*)(g_egoA + (size_t)node * EMB + t * 4);
    *(float4*)(out + (size_t)slot * EMB + t * 4) = x;
}

// ---------------- out[slot] += normalize(src_row) ----------------
__global__ void k_norm_acc(int srcSel, const int* __restrict__ items, float* __restrict__ out)
{
    int slot = blockIdx.x;
    int node = (slot < BATCH) ? items[slot] : (items[slot - BATCH] + NITEM);
    const float* row;
    if (srcSel == 0)      row = g_egoB + (size_t)node * EMB;
    else if (srcSel == 1) row = g_egoC + (size_t)node * EMB;
    else                  row = g_ego3 + (size_t)slot * EMB;

    int t = threadIdx.x;  // 128 threads
    float4 x = *(const float4*)(row + t * 4);
    float ss = x.x * x.x + x.y * x.y + x.z * x.z + x.w * x.w;
    #pragma unroll
    for (int o = 16; o; o >>= 1) ss += __shfl_xor_sync(0xffffffffu, ss, o);
    __shared__ float ws[4];
    if ((t & 31) == 0) ws[t >> 5] = ss;
    __syncthreads();
    float tot = ws[0] + ws[1] + ws[2] + ws[3];
    float inv = 1.f / fmaxf(sqrtf(tot), 1e-12f);

    float* o4 = out + (size_t)slot * EMB + t * 4;
    float4 cur = *(float4*)o4;
    cur.x += x.x * inv; cur.y += x.y * inv; cur.z += x.z * inv; cur.w += x.w * inv;
    *(float4*)o4 = cur;
}

// ---------------- launch ----------------
extern "C" void kernel_launch(void* const* d_in, const int* in_sizes, int n_in,
                              void* d_out, int out_size)
{
    const float* vis   = (const float*)d_in[0];
    const float* txt   = (const float*)d_in[1];
    const int*   er    = (const int*)  d_in[2];
    const int*   ec    = (const int*)  d_in[3];
    const float* ev    = (const float*)d_in[4];
    const int*   items = (const int*)  d_in[5];
    const float* Wgc   = (const float*)d_in[6];
    const float* bgc   = (const float*)d_in[7];
    const float* Wgc2  = (const float*)d_in[8];
    const float* bgc2  = (const float*)d_in[9];
    const float* Wbi   = (const float*)d_in[10];
    const float* bbi   = (const float*)d_in[11];
    float* out = (float*)d_out;
    int nnz = in_sizes[2];

    cudaFuncSetAttribute(k_gemm, cudaFuncAttributeMaxDynamicSharedMemorySize, GEMM_SMEM);

    const int SPMM_B = 2048;
    dim3 gGrid(2, (NNODES + 127) / 128);   // (2, 782)
    dim3 gGrid3(2, NSLOT / 128);           // (2, 64)
    dim3 wGrid(48, 16);

    // init + CSR build + weight conversions
    k_init<<<25000, 256>>>(vis, txt);
    k_zero2<<<782, 256>>>();
    k_hist<<<2048, 256>>>(er, ec, nnz);
    k_scan1<<<SCANB, 256>>>();
    k_scan2<<<1, 1024>>>();
    k_scan3<<<SCANB, 256>>>();
    k_scatter<<<2048, 256>>>(er, ec, ev, nnz);
    k_wtconv<<<wGrid, 256>>>(Wgc, Wgc2, Wbi, 0);
    k_wtconv<<<wGrid, 256>>>(Wgc + 1 * 512 * 512, Wgc2 + 1 * 512 * 512, Wbi + 1 * 512 * 512, 1);
    k_wtconv<<<wGrid, 256>>>(Wgc + 2 * 512 * 512, Wgc2 + 2 * 512 * 512, Wbi + 2 * 512 * 512, 2);

    // acc init
    k_out_init<<<NSLOT, 128>>>(items, out);

    // ---- layer 0: single-pass spmm (side+edis+h, fp16 out) -> gemm -> egoB + g_x16 ----
    k_spmm_full<<<SPMM_B, 256>>>(0, 1);
    k_gemm<<<gGrid, 512, GEMM_SMEM>>>(0, 0, bgc, bgc2, bbi, NNODES, nullptr);
    k_norm_acc<<<NSLOT, 128>>>(0, items, out);

    // ---- layer 1 ----
    k_spmm_full<<<SPMM_B, 256>>>(1, 0);
    k_gemm<<<gGrid, 512, GEMM_SMEM>>>(1, 1, bgc + 512, bgc2 + 512, bbi + 512, NNODES, nullptr);
    k_norm_acc<<<NSLOT, 128>>>(1, items, out);

    // ---- layer 2 (subset) ----
    k_spmm_slots<<<1024, 256>>>(items);
    k_gemm<<<gGrid3, 512, GEMM_SMEM>>>(2, 2, bgc + 1024, bgc2 + 1024, bbi + 1024, NSLOT, items);
    k_norm_acc<<<NSLOT, 128>>>(2, items, out);
}

// round 13
// speedup vs baseline: 1.0193x; 1.0193x over previous
#include <cuda_runtime.h>
#include <cuda_fp16.h>
#include <math.h>
#include <stdint.h>

#define NITEM   50000
#define NNODES  100000
#define NSEG    200000      // 2 * NNODES (row, col-half) segments
#define EMB     512
#define BATCH   4096
#define NSLOT   8192
#define NNZMAX  3200000
#define NCH     48          // 1536 / 32 K-chunks
#define STRB    80          // smem row stride bytes (40 halves)
#define STAGE_SZ 30720      // A 10KB + B 20KB (fp16)
#define GEMM_SMEM 62464     // 2 stages + 1KB bias
#define SCANB   782

// ---------------- static device scratch ----------------
__device__ float g_egoA[51200000];   // ego0 fp32, preserved
__device__ float g_egoB[51200000];   // layer-1 activations fp32
__device__ float g_egoC[51200000];   // layer-2 activations fp32
__device__ float g_side[51200000];   // fp32 partial (pass0 -> pass1)
__device__ float g_edis[51200000];   // fp32 partial (pass0 -> pass1)
__device__ float g_ego3[4194304];    // 8192 x 512
__device__ __half g_a16[51200000];   // fp16 ego0 (gather source, layer 0)
__device__ __half g_x16[51200000];   // fp16 current-layer ego (gather source)
__device__ __half g_s16[51200000];   // side fp16 (GEMM A seg0)
__device__ __half g_d16[51200000];   // edis fp16 (GEMM A seg1; fixed after L0)
__device__ __half g_h16[51200000];   // h    fp16 (GEMM A seg2)
__device__ int   g_rowptr[NSEG + 1];
__device__ int   g_ofs[NSEG];
__device__ int   g_bsum[1024];
__device__ int   g_boff[1024];
__device__ int   g_scol[NNZMAX];
__device__ float g_sval[NNZMAX];
__device__ __half g_wt16[3 * 512 * 1536];  // W^T fp16, [layer][N][K]

__device__ __forceinline__ uint32_t smem_u32(const void* p) {
    uint32_t a;
    asm("{ .reg .u64 t; cvta.to.shared.u64 t, %1; cvt.u32.u64 %0, t; }" : "=r"(a) : "l"(p));
    return a;
}
#define LDSM4(r0,r1,r2,r3,addr) \
    asm volatile("ldmatrix.sync.aligned.m8n8.x4.shared.b16 {%0,%1,%2,%3}, [%4];" \
                 : "=r"(r0),"=r"(r1),"=r"(r2),"=r"(r3) : "r"(addr))
#define MMAF16(d,a,b) \
    asm volatile("mma.sync.aligned.m16n8k16.row.col.f32.f16.f16.f32 " \
                 "{%0,%1,%2,%3}, {%4,%5,%6,%7}, {%8,%9}, {%0,%1,%2,%3};" \
                 : "+f"(d[0]),"+f"(d[1]),"+f"(d[2]),"+f"(d[3]) \
                 : "r"(a[0]),"r"(a[1]),"r"(a[2]),"r"(a[3]), "r"(b[0]),"r"(b[1]))
#define CP16(smaddr, gptr) \
    asm volatile("cp.async.ca.shared.global [%0], [%1], 16;" :: "r"(smaddr), "l"(gptr) : "memory")
#define CP_COMMIT() asm volatile("cp.async.commit_group;" ::: "memory")
#define CP_WAIT0()  asm volatile("cp.async.wait_group 0;" ::: "memory")

__device__ __forceinline__ uint32_t packh2(float a, float b) {
    __half2 p = __floats2half2_rn(a, b);
    return *reinterpret_cast<uint32_t*>(&p);
}
__device__ __forceinline__ uint4 pack8(const float* f) {
    uint4 u;
    u.x = packh2(f[0], f[1]); u.y = packh2(f[2], f[3]);
    u.z = packh2(f[4], f[5]); u.w = packh2(f[6], f[7]);
    return u;
}
__device__ __forceinline__ void unpack8(uint4 u, float* f) {
    const __half2* h = (const __half2*)&u;
    #pragma unroll
    for (int j = 0; j < 4; j++) {
        float2 t = __half22float2(h[j]);
        f[2 * j] = t.x; f[2 * j + 1] = t.y;
    }
}

// ---------------- init ----------------
__global__ void k_init(const float* __restrict__ vis, const float* __restrict__ txt)
{
    size_t i = (size_t)blockIdx.x * blockDim.x + threadIdx.x;
    size_t half = (size_t)NITEM * EMB / 4;
    if (i >= half) return;
    float4 v = ((const float4*)vis)[i];
    float4 t = ((const float4*)txt)[i];
    ((float4*)g_egoA)[i]        = v;
    ((float4*)g_egoA)[half + i] = t;
    __half2 hv[2] = { __floats2half2_rn(v.x, v.y), __floats2half2_rn(v.z, v.w) };
    __half2 ht[2] = { __floats2half2_rn(t.x, t.y), __floats2half2_rn(t.z, t.w) };
    *(uint2*)(g_a16 + 4 * i)          = *(uint2*)hv;
    *(uint2*)(g_a16 + 4 * (half + i)) = *(uint2*)ht;
}

__global__ void k_zero2()
{
    int i = blockIdx.x * blockDim.x + threadIdx.x;
    if (i < NSEG) g_ofs[i] = 0;
}

// ---------------- CSR build: key = 2*row + (col >= NITEM) ----------------
__global__ void k_hist(const int* __restrict__ er, const int* __restrict__ ec, int nnz)
{
    int i = blockIdx.x * blockDim.x + threadIdx.x;
    int stride = gridDim.x * blockDim.x;
    for (int e = i; e < nnz; e += stride)
        atomicAdd(&g_ofs[2 * er[e] + (ec[e] >= NITEM)], 1);
}

__global__ void k_scan1()
{
    __shared__ int sm[256];
    int t = threadIdx.x;
    int idx = blockIdx.x * 256 + t;
    int v = (idx < NSEG) ? g_ofs[idx] : 0;
    sm[t] = v;
    __syncthreads();
    #pragma unroll
    for (int off = 128; off; off >>= 1) {
        if (t < off) sm[t] += sm[t + off];
        __syncthreads();
    }
    if (t == 0) g_bsum[blockIdx.x] = sm[0];
}

__global__ void k_scan2()
{
    __shared__ int sm[1024];
    int t = threadIdx.x;
    int v = (t < SCANB) ? g_bsum[t] : 0;
    sm[t] = v;
    __syncthreads();
    #pragma unroll
    for (int off = 1; off < 1024; off <<= 1) {
        int add = (t >= off) ? sm[t - off] : 0;
        __syncthreads();
        sm[t] += add;
        __syncthreads();
    }
    if (t < SCANB) g_boff[t] = sm[t] - v;
    if (t == 1023) g_rowptr[NSEG] = sm[1023];
}

__global__ void k_scan3()
{
    __shared__ int sm[256];
    int t = threadIdx.x;
    int idx = blockIdx.x * 256 + t;
    int v = (idx < NSEG) ? g_ofs[idx] : 0;
    sm[t] = v;
    __syncthreads();
    #pragma unroll
    for (int off = 1; off < 256; off <<= 1) {
        int add = (t >= off) ? sm[t - off] : 0;
        __syncthreads();
        sm[t] += add;
        __syncthreads();
    }
    int ex = sm[t] - v + g_boff[blockIdx.x];
    if (idx < NSEG) { g_rowptr[idx] = ex; g_ofs[idx] = ex; }
}

__global__ void k_scatter(const int* __restrict__ er, const int* __restrict__ ec,
                          const float* __restrict__ ev, int nnz)
{
    int i = blockIdx.x * blockDim.x + threadIdx.x;
    int stride = gridDim.x * blockDim.x;
    for (int e = i; e < nnz; e += stride) {
        int c = ec[e];
        int pos = atomicAdd(&g_ofs[2 * er[e] + (c >= NITEM)], 1);
        g_scol[pos] = c;
        g_sval[pos] = ev[e];
    }
}

// ---------------- SpMM helpers (fp16 gathers, fp32 accumulate) ----------------
__device__ __forceinline__ void fma8(float* f, uint4 u, float v)
{
    const __half2* h = (const __half2*)&u;
    #pragma unroll
    for (int j = 0; j < 4; j++) {
        float2 t = __half22float2(h[j]);
        f[2 * j]     = fmaf(t.x, v, f[2 * j]);
        f[2 * j + 1] = fmaf(t.y, v, f[2 * j + 1]);
    }
}

__device__ __forceinline__ void accum16(const __half* __restrict__ x, int s, int e,
                                        int adj, int lane, float* f)
{
    int i = s;
    for (; i + 1 < e; i += 2) {
        int   c0 = g_scol[i] + adj, c1 = g_scol[i + 1] + adj;
        float v0 = g_sval[i],       v1 = g_sval[i + 1];
        const uint4* xa = (const uint4*)(x + (size_t)c0 * EMB);
        const uint4* xb = (const uint4*)(x + (size_t)c1 * EMB);
        uint4 a0 = __ldcg(&xa[lane]), a1 = __ldcg(&xa[lane + 32]);
        uint4 b0 = __ldcg(&xb[lane]), b1 = __ldcg(&xb[lane + 32]);
        fma8(f,     a0, v0); fma8(f + 8, a1, v0);
        fma8(f,     b0, v1); fma8(f + 8, b1, v1);
    }
    if (i < e) {
        int   c0 = g_scol[i] + adj;
        float v0 = g_sval[i];
        const uint4* xa = (const uint4*)(x + (size_t)c0 * EMB);
        uint4 a0 = __ldcg(&xa[lane]), a1 = __ldcg(&xa[lane + 32]);
        fma8(f, a0, v0); fma8(f + 8, a1, v0);
    }
}

// ---------------- SpMM full: warp per row, col-half split, 2 passes, fp16 finals ----------------
// pass0: fp32 partials to g_side/g_edis; pass1: finalize in regs, fuse h, write fp16 s/d/h.
__global__ void k_spmm_full(int srcSel, int doEdis, int pass)
{
    const __half* x16 = srcSel ? g_x16 : g_a16;
    const float* egoF = srcSel ? g_egoB : g_egoA;
    int lane = threadIdx.x & 31;
    int warp = (int)((blockIdx.x * blockDim.x + threadIdx.x) >> 5);
    int nw   = (int)((gridDim.x * blockDim.x) >> 5);

    int fi[4] = { 2 * lane, 2 * lane + 1, 2 * lane + 64, 2 * lane + 65 };

    for (int row = warp; row < NNODES; row += nw) {
        int b0 = g_rowptr[2 * row], b1 = g_rowptr[2 * row + 1], b2 = g_rowptr[2 * row + 2];
        float sacc[16];
        #pragma unroll
        for (int q = 0; q < 16; q++) sacc[q] = 0.f;
        // side: pass0 -> seg0 (c<N), pass1 -> seg1; gathers stay within x-half 'pass'
        if (pass == 0) accum16(x16, b0, b1, 0, lane, sacc);
        else           accum16(x16, b1, b2, 0, lane, sacc);

        float4* so = (float4*)(g_side + (size_t)row * EMB);
        float4* de = (float4*)(g_edis + (size_t)row * EMB);

        if (pass == 0) {
            if (doEdis) {
                float dacc[16];
                #pragma unroll
                for (int q = 0; q < 16; q++) dacc[q] = 0.f;
                accum16(x16, b1, b2, -NITEM, lane, dacc);   // oge gathers in half0
                #pragma unroll
                for (int q = 0; q < 4; q++)
                    __stcs(&de[fi[q]], *(float4*)(dacc + 4 * q));
            }
            #pragma unroll
            for (int q = 0; q < 4; q++)
                __stcs(&so[fi[q]], *(float4*)(sacc + 4 * q));
        } else {
            // finalize edis in registers
            float dacc[16];
            if (doEdis) {
                #pragma unroll
                for (int q = 0; q < 16; q++) dacc[q] = 0.f;
                accum16(x16, b0, b1, +NITEM, lane, dacc);   // oge gathers in half1
                #pragma unroll
                for (int q = 0; q < 4; q++) {
                    float4 cur = __ldcs(&de[fi[q]]);
                    dacc[4 * q + 0] += cur.x; dacc[4 * q + 1] += cur.y;
                    dacc[4 * q + 2] += cur.z; dacc[4 * q + 3] += cur.w;
                }
            } else {
                uint4* dd = (uint4*)(g_d16 + (size_t)row * EMB);
                unpack8(__ldcg(&dd[lane]),      dacc);
                unpack8(__ldcg(&dd[lane + 32]), dacc + 8);
            }
            // finalize side in registers
            #pragma unroll
            for (int q = 0; q < 4; q++) {
                float4 cur = __ldcs(&so[fi[q]]);
                sacc[4 * q + 0] += cur.x; sacc[4 * q + 1] += cur.y;
                sacc[4 * q + 2] += cur.z; sacc[4 * q + 3] += cur.w;
            }
            // h = ego*side + oge*edis
            int rowo = (row < NITEM) ? row + NITEM : row - NITEM;
            const float4* eg = (const float4*)(egoF + (size_t)row * EMB);
            const float4* og = (const float4*)(g_egoA + (size_t)rowo * EMB);
            float hv[16];
            #pragma unroll
            for (int q = 0; q < 4; q++) {
                float4 e = eg[fi[q]];
                float4 o = og[fi[q]];
                hv[4 * q + 0] = fmaf(e.x, sacc[4 * q + 0], o.x * dacc[4 * q + 0]);
                hv[4 * q + 1] = fmaf(e.y, sacc[4 * q + 1], o.y * dacc[4 * q + 1]);
                hv[4 * q + 2] = fmaf(e.z, sacc[4 * q + 2], o.z * dacc[4 * q + 2]);
                hv[4 * q + 3] = fmaf(e.w, sacc[4 * q + 3], o.w * dacc[4 * q + 3]);
            }
            // write fp16 finals
            uint4* s16 = (uint4*)(g_s16 + (size_t)row * EMB);
            uint4* h16 = (uint4*)(g_h16 + (size_t)row * EMB);
            __stcs(&s16[lane],      pack8(sacc));
            __stcs(&s16[lane + 32], pack8(sacc + 8));
            __stcs(&h16[lane],      pack8(hv));
            __stcs(&h16[lane + 32], pack8(hv + 8));
            if (doEdis) {
                uint4* d16 = (uint4*)(g_d16 + (size_t)row * EMB);
                __stcs(&d16[lane],      pack8(dacc));
                __stcs(&d16[lane + 32], pack8(dacc + 8));
            }
        }
    }
}

// ---------------- SpMM slots: warp per gathered slot (layer 2), fp16 out ----------------
__global__ void k_spmm_slots(const int* __restrict__ items)
{
    int lane = threadIdx.x & 31;
    int slot = (int)((blockIdx.x * blockDim.x + threadIdx.x) >> 5);
    if (slot >= NSLOT) return;
    int row = (slot < BATCH) ? items[slot] : (items[slot - BATCH] + NITEM);
    int b0 = g_rowptr[2 * row], b2 = g_rowptr[2 * row + 2];
    float sacc[16], dacc[16];
    #pragma unroll
    for (int q = 0; q < 16; q++) { sacc[q] = 0.f; dacc[q] = 0.f; }
    accum16(g_x16, b0, b2, 0, lane, sacc);
    uint4* dd = (uint4*)(g_d16 + (size_t)row * EMB);
    unpack8(__ldcg(&dd[lane]),      dacc);
    unpack8(__ldcg(&dd[lane + 32]), dacc + 8);

    int fi[4] = { 2 * lane, 2 * lane + 1, 2 * lane + 64, 2 * lane + 65 };
    int rowo = (row < NITEM) ? row + NITEM : row - NITEM;
    const float4* eg = (const float4*)(g_egoC + (size_t)row * EMB);
    const float4* og = (const float4*)(g_egoA + (size_t)rowo * EMB);
    float hv[16];
    #pragma unroll
    for (int q = 0; q < 4; q++) {
        float4 e = eg[fi[q]];
        float4 o = og[fi[q]];
        hv[4 * q + 0] = fmaf(e.x, sacc[4 * q + 0], o.x * dacc[4 * q + 0]);
        hv[4 * q + 1] = fmaf(e.y, sacc[4 * q + 1], o.y * dacc[4 * q + 1]);
        hv[4 * q + 2] = fmaf(e.z, sacc[4 * q + 2], o.z * dacc[4 * q + 2]);
        hv[4 * q + 3] = fmaf(e.w, sacc[4 * q + 3], o.w * dacc[4 * q + 3]);
    }
    uint4* s16 = (uint4*)(g_s16 + (size_t)row * EMB);
    uint4* h16 = (uint4*)(g_h16 + (size_t)row * EMB);
    s16[lane]      = pack8(sacc);
    s16[lane + 32] = pack8(sacc + 8);
    h16[lane]      = pack8(hv);
    h16[lane + 32] = pack8(hv + 8);
}

// ---------------- weight transpose + fp16 convert ----------------
__global__ void k_wtconv(const float* __restrict__ Wgc, const float* __restrict__ Wgc2,
                         const float* __restrict__ Wbi, int layer)
{
    __shared__ float t[32][33];
    int kb = blockIdx.x * 32;
    int nb = blockIdx.y * 32;
    int tx = threadIdx.x & 31, ty = threadIdx.x >> 5;
    int seg = kb >> 9, kloc = kb & 511;
    const float* W = (seg == 0) ? Wgc : (seg == 1) ? Wgc2 : Wbi;
    size_t lbase = (size_t)layer * 512 * 1536;
    #pragma unroll
    for (int j = 0; j < 4; j++)
        t[ty + 8 * j][tx] = W[(size_t)(kloc + ty + 8 * j) * 512 + nb + tx];
    __syncthreads();
    #pragma unroll
    for (int j = 0; j < 4; j++) {
        int n = nb + ty + 8 * j;
        g_wt16[lbase + (size_t)n * 1536 + kb + tx] = __float2half_rn(t[tx][ty + 8 * j]);
    }
}

// ---------------- mma.sync fp16 GEMM, 128x256, all-cp.async ----------------
// A = [s16 | d16 | h16]; outSel: 0=egoB 1=egoC 2=ego3
__global__ void __launch_bounds__(512)
k_gemm(int outSel, int layer,
       const float* __restrict__ bgc, const float* __restrict__ bgc2,
       const float* __restrict__ bbi,
       int M, const int* __restrict__ items)
{
    extern __shared__ __align__(16) char smbuf[];
    const uint32_t OA = 0, OB = 10240;
    float* biasP = (float*)(smbuf + 2 * STAGE_SZ);
    uint32_t smb = smem_u32(smbuf);

    int tid = threadIdx.x;
    int wid = tid >> 5, lid = tid & 31;
    int col0 = blockIdx.x * 256;
    int row0 = blockIdx.y * 128;
    int wM = wid >> 2, wN = wid & 3;

    if (tid < 256) {
        int c = col0 + tid;
        biasP[tid] = bgc[c] + bgc2[c] + bbi[c];
    }

    float* Cout = (outSel == 0) ? g_egoB : (outSel == 1) ? g_egoC : g_ego3;
    const __half* wt = g_wt16 + (size_t)layer * 512 * 1536;

    int mA = tid >> 2;
    int kq8 = (tid & 3) * 8;
    int node;
    {
        int g0 = row0 + mA;
        int s0 = (g0 < M) ? g0 : (M - 1);
        node = items ? ((s0 < BATCH) ? items[s0] : (items[s0 - BATCH] + NITEM)) : s0;
    }
    int nB = tid >> 1, kqB = (tid & 1) * 16;

    float acc[2][8][4];
    #pragma unroll
    for (int mt = 0; mt < 2; mt++)
        #pragma unroll
        for (int nt = 0; nt < 8; nt++)
            #pragma unroll
            for (int q = 0; q < 4; q++) acc[mt][nt][q] = 0.f;

    auto cpasyncA = [&](int c) {
        uint32_t base = smb + (c & 1) * STAGE_SZ;
        int seg = c >> 4;
        int kloc = (c & 15) * 32;
        const __half* src = (seg == 0) ? g_s16 : (seg == 1) ? g_d16 : g_h16;
        const char* gp = (const char*)(src + (size_t)node * EMB + kloc + kq8);
        CP16(base + OA + mA * STRB + (tid & 3) * 16, gp);
    };
    auto cpasyncB = [&](int c) {
        uint32_t base = smb + (c & 1) * STAGE_SZ;
        const char* gw = (const char*)(wt + (size_t)(col0 + nB) * 1536 + c * 32 + kqB);
        uint32_t bd = base + OB + nB * STRB + kqB * 2;
        CP16(bd, gw);
        CP16(bd + 16, gw + 16);
    };

    uint32_t aOff = (uint32_t)((wM * 32 + (lid & 15)) * STRB + (lid >> 4) * 16);
    uint32_t bOff[4];
    #pragma unroll
    for (int p = 0; p < 4; p++)
        bOff[p] = (uint32_t)((wN * 64 + p * 16 + (lid & 7) + ((lid >> 4) << 3)) * STRB + (((lid >> 3) & 1) << 4));

    cpasyncA(0);
    cpasyncB(0);
    CP_COMMIT();
    CP_WAIT0();
    __syncthreads();

    for (int c = 0; c < NCH; c++) {
        if (c + 1 < NCH) { cpasyncA(c + 1); cpasyncB(c + 1); CP_COMMIT(); }
        uint32_t sb = smb + (c & 1) * STAGE_SZ;
        #pragma unroll
        for (int kk = 0; kk < 2; kk++) {
            uint32_t ko = kk * 32;
            uint32_t ah[2][4];
            LDSM4(ah[0][0], ah[0][1], ah[0][2], ah[0][3], sb + OA + aOff + ko);
            LDSM4(ah[1][0], ah[1][1], ah[1][2], ah[1][3], sb + OA + aOff + 16 * STRB + ko);
            #pragma unroll
            for (int p = 0; p < 4; p++) {
                uint32_t b4[4];
                LDSM4(b4[0], b4[1], b4[2], b4[3], sb + OB + bOff[p] + ko);
                #pragma unroll
                for (int mt = 0; mt < 2; mt++) {
                    MMAF16(acc[mt][2 * p],     ah[mt], (b4 + 0));
                    MMAF16(acc[mt][2 * p + 1], ah[mt], (b4 + 2));
                }
            }
        }
        if (c + 1 < NCH) {
            CP_WAIT0();
            __syncthreads();
        }
    }

    // ---- epilogue: bias + leaky_relu (fp32 out + fp16 gather copy) ----
    int rA = lid >> 2;
    int cA = (lid & 3) * 2;
    #pragma unroll
    for (int mt = 0; mt < 2; mt++) {
        #pragma unroll
        for (int half = 0; half < 2; half++) {
            int gr = row0 + wM * 32 + mt * 16 + rA + half * 8;
            if (gr < M) {
                float* cp = Cout + (size_t)gr * EMB + col0 + wN * 64;
                __half* hp = g_x16 + (size_t)gr * EMB + col0 + wN * 64;
                #pragma unroll
                for (int nt = 0; nt < 8; nt++) {
                    int cc = nt * 8 + cA;
                    float x0 = acc[mt][nt][half * 2 + 0] + biasP[wN * 64 + cc];
                    float x1 = acc[mt][nt][half * 2 + 1] + biasP[wN * 64 + cc + 1];
                    float2 o;
                    o.x = (x0 > 0.f) ? x0 : 0.2f * x0;
                    o.y = (x1 > 0.f) ? x1 : 0.2f * x1;
                    *(float2*)(cp + cc) = o;
                    if (outSel < 2)
                        *(__half2*)(hp + cc) = __floats2half2_rn(o.x, o.y);
                }
            }
        }
    }
}

// ---------------- out[slot] = ego0[node]  (acc init) ----------------
__global__ void k_out_init(const int* __restrict__ items, float* __restrict__ out)
{
    int slot = blockIdx.x;
    int node = (slot < BATCH) ? items[slot] : (items[slot - BATCH] + NITEM);
    int t = threadIdx.x;
    float4 x = *(const float4*)(g_egoA + (size_t)node * EMB + t * 4);
    *(float4*)(out + (size_t)slot * EMB + t * 4) = x;
}

// ---------------- out[slot] += normalize(src_row) ----------------
__global__ void k_norm_acc(int srcSel, const int* __restrict__ items, float* __restrict__ out)
{
    int slot = blockIdx.x;
    int node = (slot < BATCH) ? items[slot] : (items[slot - BATCH] + NITEM);
    const float* row;
    if (srcSel == 0)      row = g_egoB + (size_t)node * EMB;
    else if (srcSel == 1) row = g_egoC + (size_t)node * EMB;
    else                  row = g_ego3 + (size_t)slot * EMB;

    int t = threadIdx.x;  // 128 threads
    float4 x = *(const float4*)(row + t * 4);
    float ss = x.x * x.x + x.y * x.y + x.z * x.z + x.w * x.w;
    #pragma unroll
    for (int o = 16; o; o >>= 1) ss += __shfl_xor_sync(0xffffffffu, ss, o);
    __shared__ float ws[4];
    if ((t & 31) == 0) ws[t >> 5] = ss;
    __syncthreads();
    float tot = ws[0] + ws[1] + ws[2] + ws[3];
    float inv = 1.f / fmaxf(sqrtf(tot), 1e-12f);

    float* o4 = out + (size_t)slot * EMB + t * 4;
    float4 cur = *(float4*)o4;
    cur.x += x.x * inv; cur.y += x.y * inv; cur.z += x.z * inv; cur.w += x.w * inv;
    *(float4*)o4 = cur;
}

// ---------------- launch ----------------
extern "C" void kernel_launch(void* const* d_in, const int* in_sizes, int n_in,
                              void* d_out, int out_size)
{
    const float* vis   = (const float*)d_in[0];
    const float* txt   = (const float*)d_in[1];
    const int*   er    = (const int*)  d_in[2];
    const int*   ec    = (const int*)  d_in[3];
    const float* ev    = (const float*)d_in[4];
    const int*   items = (const int*)  d_in[5];
    const float* Wgc   = (const float*)d_in[6];
    const float* bgc   = (const float*)d_in[7];
    const float* Wgc2  = (const float*)d_in[8];
    const float* bgc2  = (const float*)d_in[9];
    const float* Wbi   = (const float*)d_in[10];
    const float* bbi   = (const float*)d_in[11];
    float* out = (float*)d_out;
    int nnz = in_sizes[2];

    cudaFuncSetAttribute(k_gemm, cudaFuncAttributeMaxDynamicSharedMemorySize, GEMM_SMEM);

    const int SPMM_B = 2048;
    dim3 gGrid(2, (NNODES + 127) / 128);   // (2, 782)
    dim3 gGrid3(2, NSLOT / 128);           // (2, 64)
    dim3 wGrid(48, 16);

    // init + CSR build + weight conversions
    k_init<<<25000, 256>>>(vis, txt);
    k_zero2<<<782, 256>>>();
    k_hist<<<2048, 256>>>(er, ec, nnz);
    k_scan1<<<SCANB, 256>>>();
    k_scan2<<<1, 1024>>>();
    k_scan3<<<SCANB, 256>>>();
    k_scatter<<<2048, 256>>>(er, ec, ev, nnz);
    k_wtconv<<<wGrid, 256>>>(Wgc, Wgc2, Wbi, 0);
    k_wtconv<<<wGrid, 256>>>(Wgc + 1 * 512 * 512, Wgc2 + 1 * 512 * 512, Wbi + 1 * 512 * 512, 1);
    k_wtconv<<<wGrid, 256>>>(Wgc + 2 * 512 * 512, Wgc2 + 2 * 512 * 512, Wbi + 2 * 512 * 512, 2);

    // acc init
    k_out_init<<<NSLOT, 128>>>(items, out);

    // ---- layer 0: 2-pass spmm (L2-resident halves), fp16 finals -> gemm -> egoB + g_x16 ----
    k_spmm_full<<<SPMM_B, 256>>>(0, 1, 0);
    k_spmm_full<<<SPMM_B, 256>>>(0, 1, 1);
    k_gemm<<<gGrid, 512, GEMM_SMEM>>>(0, 0, bgc, bgc2, bbi, NNODES, nullptr);
    k_norm_acc<<<NSLOT, 128>>>(0, items, out);

    // ---- layer 1 ----
    k_spmm_full<<<SPMM_B, 256>>>(1, 0, 0);
    k_spmm_full<<<SPMM_B, 256>>>(1, 0, 1);
    k_gemm<<<gGrid, 512, GEMM_SMEM>>>(1, 1, bgc + 512, bgc2 + 512, bbi + 512, NNODES, nullptr);
    k_norm_acc<<<NSLOT, 128>>>(1, items, out);

    // ---- layer 2 (subset) ----
    k_spmm_slots<<<1024, 256>>>(items);
    k_gemm<<<gGrid3, 512, GEMM_SMEM>>>(2, 2, bgc + 1024, bgc2 + 1024, bbi + 1024, NSLOT, items);
    k_norm_acc<<<NSLOT, 128>>>(2, items, out);
}

// round 14
// speedup vs baseline: 1.1731x; 1.1509x over previous
#include <cuda_runtime.h>
#include <cuda_fp16.h>
#include <math.h>
#include <stdint.h>

#define NITEM   50000
#define NNODES  100000
#define NSEG    200000      // 2 * NNODES (row, col-half) segments
#define EMB     512
#define BATCH   4096
#define NSLOT   8192
#define NNZMAX  3200000
#define NCH     48          // 1536 / 32 K-chunks
#define STRB    80          // smem row stride bytes (40 halves)
#define STAGE_SZ 30720      // A 10KB + B 20KB (fp16)
#define NSTAGE  3
#define GEMM_SMEM (NSTAGE * STAGE_SZ + 1024)
#define SCANB   782

// ---------------- static device scratch ----------------
__device__ float g_side[51200000];   // fp32 partial (pass0 -> pass1)
__device__ float g_edis[51200000];   // fp32 partial (pass0 -> pass1)
__device__ float g_ego3[4194304];    // 8192 x 512 (layer-2 out, fp32)
__device__ __half g_a16[51200000];   // fp16 ego0 (gather + oge source)
__device__ __half g_x16[51200000];   // fp16 current-layer ego
__device__ __half g_s16[51200000];   // side fp16 (GEMM A seg0)
__device__ __half g_d16[51200000];   // edis fp16 (GEMM A seg1; fixed after L0)
__device__ __half g_h16[51200000];   // h    fp16 (GEMM A seg2)
__device__ int   g_rowptr[NSEG + 1];
__device__ int   g_ofs[NSEG];
__device__ int   g_bsum[1024];
__device__ int   g_boff[1024];
__device__ int   g_scol[NNZMAX];
__device__ float g_sval[NNZMAX];
__device__ __half g_wt16[3 * 512 * 1536];  // W^T fp16, [layer][N][K]

__device__ __forceinline__ uint32_t smem_u32(const void* p) {
    uint32_t a;
    asm("{ .reg .u64 t; cvta.to.shared.u64 t, %1; cvt.u32.u64 %0, t; }" : "=r"(a) : "l"(p));
    return a;
}
#define LDSM4(r0,r1,r2,r3,addr) \
    asm volatile("ldmatrix.sync.aligned.m8n8.x4.shared.b16 {%0,%1,%2,%3}, [%4];" \
                 : "=r"(r0),"=r"(r1),"=r"(r2),"=r"(r3) : "r"(addr))
#define MMAF16(d,a,b) \
    asm volatile("mma.sync.aligned.m16n8k16.row.col.f32.f16.f16.f32 " \
                 "{%0,%1,%2,%3}, {%4,%5,%6,%7}, {%8,%9}, {%0,%1,%2,%3};" \
                 : "+f"(d[0]),"+f"(d[1]),"+f"(d[2]),"+f"(d[3]) \
                 : "r"(a[0]),"r"(a[1]),"r"(a[2]),"r"(a[3]), "r"(b[0]),"r"(b[1]))
#define CP16(smaddr, gptr) \
    asm volatile("cp.async.ca.shared.global [%0], [%1], 16;" :: "r"(smaddr), "l"(gptr) : "memory")
#define CP_COMMIT() asm volatile("cp.async.commit_group;" ::: "memory")
#define CP_WAIT(n)  asm volatile("cp.async.wait_group %0;" :: "n"(n) : "memory")

__device__ __forceinline__ uint32_t packh2(float a, float b) {
    __half2 p = __floats2half2_rn(a, b);
    return *reinterpret_cast<uint32_t*>(&p);
}
__device__ __forceinline__ uint4 pack8(const float* f) {
    uint4 u;
    u.x = packh2(f[0], f[1]); u.y = packh2(f[2], f[3]);
    u.z = packh2(f[4], f[5]); u.w = packh2(f[6], f[7]);
    return u;
}
__device__ __forceinline__ void unpack8(uint4 u, float* f) {
    const __half2* h = (const __half2*)&u;
    #pragma unroll
    for (int j = 0; j < 4; j++) {
        float2 t = __half22float2(h[j]);
        f[2 * j] = t.x; f[2 * j + 1] = t.y;
    }
}

// ---------------- init: a16 = fp16([vision;text]) ----------------
__global__ void k_init(const float* __restrict__ vis, const float* __restrict__ txt)
{
    size_t i = (size_t)blockIdx.x * blockDim.x + threadIdx.x;
    size_t half = (size_t)NITEM * EMB / 4;
    if (i >= half) return;
    float4 v = ((const float4*)vis)[i];
    float4 t = ((const float4*)txt)[i];
    __half2 hv[2] = { __floats2half2_rn(v.x, v.y), __floats2half2_rn(v.z, v.w) };
    __half2 ht[2] = { __floats2half2_rn(t.x, t.y), __floats2half2_rn(t.z, t.w) };
    *(uint2*)(g_a16 + 4 * i)          = *(uint2*)hv;
    *(uint2*)(g_a16 + 4 * (half + i)) = *(uint2*)ht;
}

__global__ void k_zero2()
{
    int i = blockIdx.x * blockDim.x + threadIdx.x;
    if (i < NSEG) g_ofs[i] = 0;
}

// ---------------- CSR build: key = 2*row + (col >= NITEM) ----------------
__global__ void k_hist(const int* __restrict__ er, const int* __restrict__ ec, int nnz)
{
    int i = blockIdx.x * blockDim.x + threadIdx.x;
    int stride = gridDim.x * blockDim.x;
    for (int e = i; e < nnz; e += stride)
        atomicAdd(&g_ofs[2 * er[e] + (ec[e] >= NITEM)], 1);
}

__global__ void k_scan1()
{
    __shared__ int sm[256];
    int t = threadIdx.x;
    int idx = blockIdx.x * 256 + t;
    int v = (idx < NSEG) ? g_ofs[idx] : 0;
    sm[t] = v;
    __syncthreads();
    #pragma unroll
    for (int off = 128; off; off >>= 1) {
        if (t < off) sm[t] += sm[t + off];
        __syncthreads();
    }
    if (t == 0) g_bsum[blockIdx.x] = sm[0];
}

__global__ void k_scan2()
{
    __shared__ int sm[1024];
    int t = threadIdx.x;
    int v = (t < SCANB) ? g_bsum[t] : 0;
    sm[t] = v;
    __syncthreads();
    #pragma unroll
    for (int off = 1; off < 1024; off <<= 1) {
        int add = (t >= off) ? sm[t - off] : 0;
        __syncthreads();
        sm[t] += add;
        __syncthreads();
    }
    if (t < SCANB) g_boff[t] = sm[t] - v;
    if (t == 1023) g_rowptr[NSEG] = sm[1023];
}

__global__ void k_scan3()
{
    __shared__ int sm[256];
    int t = threadIdx.x;
    int idx = blockIdx.x * 256 + t;
    int v = (idx < NSEG) ? g_ofs[idx] : 0;
    sm[t] = v;
    __syncthreads();
    #pragma unroll
    for (int off = 1; off < 256; off <<= 1) {
        int add = (t >= off) ? sm[t - off] : 0;
        __syncthreads();
        sm[t] += add;
        __syncthreads();
    }
    int ex = sm[t] - v + g_boff[blockIdx.x];
    if (idx < NSEG) { g_rowptr[idx] = ex; g_ofs[idx] = ex; }
}

__global__ void k_scatter(const int* __restrict__ er, const int* __restrict__ ec,
                          const float* __restrict__ ev, int nnz)
{
    int i = blockIdx.x * blockDim.x + threadIdx.x;
    int stride = gridDim.x * blockDim.x;
    for (int e = i; e < nnz; e += stride) {
        int c = ec[e];
        int pos = atomicAdd(&g_ofs[2 * er[e] + (c >= NITEM)], 1);
        g_scol[pos] = c;
        g_sval[pos] = ev[e];
    }
}

// ---------------- SpMM helpers (fp16 gathers, fp32 accumulate) ----------------
__device__ __forceinline__ void fma8(float* f, uint4 u, float v)
{
    const __half2* h = (const __half2*)&u;
    #pragma unroll
    for (int j = 0; j < 4; j++) {
        float2 t = __half22float2(h[j]);
        f[2 * j]     = fmaf(t.x, v, f[2 * j]);
        f[2 * j + 1] = fmaf(t.y, v, f[2 * j + 1]);
    }
}

__device__ __forceinline__ void accum16(const __half* __restrict__ x, int s, int e,
                                        int adj, int lane, float* f)
{
    int i = s;
    for (; i + 1 < e; i += 2) {
        int   c0 = g_scol[i] + adj, c1 = g_scol[i + 1] + adj;
        float v0 = g_sval[i],       v1 = g_sval[i + 1];
        const uint4* xa = (const uint4*)(x + (size_t)c0 * EMB);
        const uint4* xb = (const uint4*)(x + (size_t)c1 * EMB);
        uint4 a0 = __ldcg(&xa[lane]), a1 = __ldcg(&xa[lane + 32]);
        uint4 b0 = __ldcg(&xb[lane]), b1 = __ldcg(&xb[lane + 32]);
        fma8(f,     a0, v0); fma8(f + 8, a1, v0);
        fma8(f,     b0, v1); fma8(f + 8, b1, v1);
    }
    if (i < e) {
        int   c0 = g_scol[i] + adj;
        float v0 = g_sval[i];
        const uint4* xa = (const uint4*)(x + (size_t)c0 * EMB);
        uint4 a0 = __ldcg(&xa[lane]), a1 = __ldcg(&xa[lane + 32]);
        fma8(f, a0, v0); fma8(f + 8, a1, v0);
    }
}

// ---------------- SpMM full: warp per row, col-half split, 2 passes, fp16 finals ----------------
// srcSel: 0 = layer0 (x = g_a16), 1 = layer1 (x = g_x16).
// pass0: fp32 partials to g_side/g_edis; pass1: finalize in regs, fuse h, write fp16 s/d/h.
__global__ void k_spmm_full(int srcSel, int doEdis, int pass)
{
    const __half* x16 = srcSel ? g_x16 : g_a16;
    int lane = threadIdx.x & 31;
    int warp = (int)((blockIdx.x * blockDim.x + threadIdx.x) >> 5);
    int nw   = (int)((gridDim.x * blockDim.x) >> 5);

    int fi[4] = { 2 * lane, 2 * lane + 1, 2 * lane + 64, 2 * lane + 65 };

    for (int row = warp; row < NNODES; row += nw) {
        int b0 = g_rowptr[2 * row], b1 = g_rowptr[2 * row + 1], b2 = g_rowptr[2 * row + 2];
        float sacc[16];
        #pragma unroll
        for (int q = 0; q < 16; q++) sacc[q] = 0.f;
        if (pass == 0) accum16(x16, b0, b1, 0, lane, sacc);
        else           accum16(x16, b1, b2, 0, lane, sacc);

        float4* so = (float4*)(g_side + (size_t)row * EMB);
        float4* de = (float4*)(g_edis + (size_t)row * EMB);

        if (pass == 0) {
            if (doEdis) {
                float dacc[16];
                #pragma unroll
                for (int q = 0; q < 16; q++) dacc[q] = 0.f;
                accum16(x16, b1, b2, -NITEM, lane, dacc);   // oge gathers in half0
                #pragma unroll
                for (int q = 0; q < 4; q++)
                    __stcs(&de[fi[q]], *(float4*)(dacc + 4 * q));
            }
            #pragma unroll
            for (int q = 0; q < 4; q++)
                __stcs(&so[fi[q]], *(float4*)(sacc + 4 * q));
        } else {
            // finalize edis in registers
            float dacc[16];
            if (doEdis) {
                #pragma unroll
                for (int q = 0; q < 16; q++) dacc[q] = 0.f;
                accum16(x16, b0, b1, +NITEM, lane, dacc);   // oge gathers in half1
                #pragma unroll
                for (int q = 0; q < 4; q++) {
                    float4 cur = __ldcs(&de[fi[q]]);
                    dacc[4 * q + 0] += cur.x; dacc[4 * q + 1] += cur.y;
                    dacc[4 * q + 2] += cur.z; dacc[4 * q + 3] += cur.w;
                }
            } else {
                uint4* dd = (uint4*)(g_d16 + (size_t)row * EMB);
                unpack8(__ldcg(&dd[lane]),      dacc);
                unpack8(__ldcg(&dd[lane + 32]), dacc + 8);
            }
            // finalize side in registers
            #pragma unroll
            for (int q = 0; q < 4; q++) {
                float4 cur = __ldcs(&so[fi[q]]);
                sacc[4 * q + 0] += cur.x; sacc[4 * q + 1] += cur.y;
                sacc[4 * q + 2] += cur.z; sacc[4 * q + 3] += cur.w;
            }
            // ego/oge from fp16 arrays (L2-hot)
            int rowo = (row < NITEM) ? row + NITEM : row - NITEM;
            const uint4* eg = (const uint4*)(x16 + (size_t)row * EMB);
            const uint4* og = (const uint4*)(g_a16 + (size_t)rowo * EMB);
            float egv[16], ogv[16];
            unpack8(eg[lane], egv);      unpack8(eg[lane + 32], egv + 8);
            unpack8(og[lane], ogv);      unpack8(og[lane + 32], ogv + 8);
            float hv[16];
            #pragma unroll
            for (int q = 0; q < 16; q++)
                hv[q] = fmaf(egv[q], sacc[q], ogv[q] * dacc[q]);
            // write fp16 finals
            uint4* s16 = (uint4*)(g_s16 + (size_t)row * EMB);
            uint4* h16 = (uint4*)(g_h16 + (size_t)row * EMB);
            __stcs(&s16[lane],      pack8(sacc));
            __stcs(&s16[lane + 32], pack8(sacc + 8));
            __stcs(&h16[lane],      pack8(hv));
            __stcs(&h16[lane + 32], pack8(hv + 8));
            if (doEdis) {
                uint4* d16 = (uint4*)(g_d16 + (size_t)row * EMB);
                __stcs(&d16[lane],      pack8(dacc));
                __stcs(&d16[lane + 32], pack8(dacc + 8));
            }
        }
    }
}

// ---------------- SpMM slots: warp per gathered slot (layer 2), fp16 out ----------------
__global__ void k_spmm_slots(const int* __restrict__ items)
{
    int lane = threadIdx.x & 31;
    int slot = (int)((blockIdx.x * blockDim.x + threadIdx.x) >> 5);
    if (slot >= NSLOT) return;
    int row = (slot < BATCH) ? items[slot] : (items[slot - BATCH] + NITEM);
    int b0 = g_rowptr[2 * row], b2 = g_rowptr[2 * row + 2];
    float sacc[16], dacc[16];
    #pragma unroll
    for (int q = 0; q < 16; q++) { sacc[q] = 0.f; dacc[q] = 0.f; }
    accum16(g_x16, b0, b2, 0, lane, sacc);
    uint4* dd = (uint4*)(g_d16 + (size_t)row * EMB);
    unpack8(__ldcg(&dd[lane]),      dacc);
    unpack8(__ldcg(&dd[lane + 32]), dacc + 8);

    int rowo = (row < NITEM) ? row + NITEM : row - NITEM;
    const uint4* eg = (const uint4*)(g_x16 + (size_t)row * EMB);
    const uint4* og = (const uint4*)(g_a16 + (size_t)rowo * EMB);
    float egv[16], ogv[16];
    unpack8(eg[lane], egv);      unpack8(eg[lane + 32], egv + 8);
    unpack8(og[lane], ogv);      unpack8(og[lane + 32], ogv + 8);
    float hv[16];
    #pragma unroll
    for (int q = 0; q < 16; q++)
        hv[q] = fmaf(egv[q], sacc[q], ogv[q] * dacc[q]);

    uint4* s16 = (uint4*)(g_s16 + (size_t)row * EMB);
    uint4* h16 = (uint4*)(g_h16 + (size_t)row * EMB);
    s16[lane]      = pack8(sacc);
    s16[lane + 32] = pack8(sacc + 8);
    h16[lane]      = pack8(hv);
    h16[lane + 32] = pack8(hv + 8);
}

// ---------------- weight transpose + fp16 convert ----------------
__global__ void k_wtconv(const float* __restrict__ Wgc, const float* __restrict__ Wgc2,
                         const float* __restrict__ Wbi, int layer)
{
    __shared__ float t[32][33];
    int kb = blockIdx.x * 32;
    int nb = blockIdx.y * 32;
    int tx = threadIdx.x & 31, ty = threadIdx.x >> 5;
    int seg = kb >> 9, kloc = kb & 511;
    const float* W = (seg == 0) ? Wgc : (seg == 1) ? Wgc2 : Wbi;
    size_t lbase = (size_t)layer * 512 * 1536;
    #pragma unroll
    for (int j = 0; j < 4; j++)
        t[ty + 8 * j][tx] = W[(size_t)(kloc + ty + 8 * j) * 512 + nb + tx];
    __syncthreads();
    #pragma unroll
    for (int j = 0; j < 4; j++) {
        int n = nb + ty + 8 * j;
        g_wt16[lbase + (size_t)n * 1536 + kb + tx] = __float2half_rn(t[tx][ty + 8 * j]);
    }
}

// ---------------- mma.sync fp16 GEMM, 128x256, 3-stage cp.async pipeline ----------------
// A = [s16 | d16 | h16]; outSel: 0/1 -> g_x16 (fp16 only), 2 -> g_ego3 (fp32)
__global__ void __launch_bounds__(512)
k_gemm(int outSel, int layer,
       const float* __restrict__ bgc, const float* __restrict__ bgc2,
       const float* __restrict__ bbi,
       int M, const int* __restrict__ items)
{
    extern __shared__ __align__(16) char smbuf[];
    const uint32_t OA = 0, OB = 10240;
    float* biasP = (float*)(smbuf + NSTAGE * STAGE_SZ);
    uint32_t smb = smem_u32(smbuf);

    int tid = threadIdx.x;
    int wid = tid >> 5, lid = tid & 31;
    int col0 = blockIdx.x * 256;
    int row0 = blockIdx.y * 128;
    int wM = wid >> 2, wN = wid & 3;

    if (tid < 256) {
        int c = col0 + tid;
        biasP[tid] = bgc[c] + bgc2[c] + bbi[c];
    }

    const __half* wt = g_wt16 + (size_t)layer * 512 * 1536;

    int mA = tid >> 2;
    int kq8 = (tid & 3) * 8;
    int node;
    {
        int g0 = row0 + mA;
        int s0 = (g0 < M) ? g0 : (M - 1);
        node = items ? ((s0 < BATCH) ? items[s0] : (items[s0 - BATCH] + NITEM)) : s0;
    }
    int nB = tid >> 1, kqB = (tid & 1) * 16;

    float acc[2][8][4];
    #pragma unroll
    for (int mt = 0; mt < 2; mt++)
        #pragma unroll
        for (int nt = 0; nt < 8; nt++)
            #pragma unroll
            for (int q = 0; q < 4; q++) acc[mt][nt][q] = 0.f;

    auto cpstage = [&](int c) {
        uint32_t base = smb + (c % NSTAGE) * STAGE_SZ;
        int seg = c >> 4;
        int kloc = (c & 15) * 32;
        const __half* src = (seg == 0) ? g_s16 : (seg == 1) ? g_d16 : g_h16;
        const char* gp = (const char*)(src + (size_t)node * EMB + kloc + kq8);
        CP16(base + OA + mA * STRB + (tid & 3) * 16, gp);
        const char* gw = (const char*)(wt + (size_t)(col0 + nB) * 1536 + c * 32 + kqB);
        uint32_t bd = base + OB + nB * STRB + kqB * 2;
        CP16(bd, gw);
        CP16(bd + 16, gw + 16);
    };

    uint32_t aOff = (uint32_t)((wM * 32 + (lid & 15)) * STRB + (lid >> 4) * 16);
    uint32_t bOff[4];
    #pragma unroll
    for (int p = 0; p < 4; p++)
        bOff[p] = (uint32_t)((wN * 64 + p * 16 + (lid & 7) + ((lid >> 4) << 3)) * STRB + (((lid >> 3) & 1) << 4));

    cpstage(0); CP_COMMIT();
    cpstage(1); CP_COMMIT();

    for (int c = 0; c < NCH; c++) {
        CP_WAIT(1);          // group c complete (pending: c+1)
        __syncthreads();
        if (c + 2 < NCH) { cpstage(c + 2); CP_COMMIT(); }
        else { CP_COMMIT(); }   // keep group accounting uniform
        uint32_t sb = smb + (c % NSTAGE) * STAGE_SZ;
        #pragma unroll
        for (int kk = 0; kk < 2; kk++) {
            uint32_t ko = kk * 32;
            uint32_t ah[2][4];
            LDSM4(ah[0][0], ah[0][1], ah[0][2], ah[0][3], sb + OA + aOff + ko);
            LDSM4(ah[1][0], ah[1][1], ah[1][2], ah[1][3], sb + OA + aOff + 16 * STRB + ko);
            #pragma unroll
            for (int p = 0; p < 4; p++) {
                uint32_t b4[4];
                LDSM4(b4[0], b4[1], b4[2], b4[3], sb + OB + bOff[p] + ko);
                #pragma unroll
                for (int mt = 0; mt < 2; mt++) {
                    MMAF16(acc[mt][2 * p],     ah[mt], (b4 + 0));
                    MMAF16(acc[mt][2 * p + 1], ah[mt], (b4 + 2));
                }
            }
        }
        __syncthreads();     // all warps done reading stage c before it is overwritten
    }

    // ---- epilogue: bias + leaky_relu ----
    int rA = lid >> 2;
    int cA = (lid & 3) * 2;
    #pragma unroll
    for (int mt = 0; mt < 2; mt++) {
        #pragma unroll
        for (int half = 0; half < 2; half++) {
            int gr = row0 + wM * 32 + mt * 16 + rA + half * 8;
            if (gr < M) {
                float* cp = g_ego3 + (size_t)gr * EMB + col0 + wN * 64;
                __half* hp = g_x16 + (size_t)gr * EMB + col0 + wN * 64;
                #pragma unroll
                for (int nt = 0; nt < 8; nt++) {
                    int cc = nt * 8 + cA;
                    float x0 = acc[mt][nt][half * 2 + 0] + biasP[wN * 64 + cc];
                    float x1 = acc[mt][nt][half * 2 + 1] + biasP[wN * 64 + cc + 1];
                    float2 o;
                    o.x = (x0 > 0.f) ? x0 : 0.2f * x0;
                    o.y = (x1 > 0.f) ? x1 : 0.2f * x1;
                    if (outSel == 2) *(float2*)(cp + cc) = o;
                    else             *(__half2*)(hp + cc) = __floats2half2_rn(o.x, o.y);
                }
            }
        }
    }
}

// ---------------- out[slot] = ego0[node]  (exact fp32 from inputs) ----------------
__global__ void k_out_init(const float* __restrict__ vis, const float* __restrict__ txt,
                           const int* __restrict__ items, float* __restrict__ out)
{
    int slot = blockIdx.x;
    int node = (slot < BATCH) ? items[slot] : (items[slot - BATCH] + NITEM);
    const float* src = (node < NITEM) ? (vis + (size_t)node * EMB)
                                      : (txt + (size_t)(node - NITEM) * EMB);
    int t = threadIdx.x;
    float4 x = *(const float4*)(src + t * 4);
    *(float4*)(out + (size_t)slot * EMB + t * 4) = x;
}

// ---------------- out[slot] += normalize(src_row) ----------------
// srcSel: 0/1 -> g_x16[node] (fp16), 2 -> g_ego3[slot] (fp32)
__global__ void k_norm_acc(int srcSel, const int* __restrict__ items, float* __restrict__ out)
{
    int slot = blockIdx.x;
    int node = (slot < BATCH) ? items[slot] : (items[slot - BATCH] + NITEM);

    int t = threadIdx.x;  // 128 threads, 4 values each
    float xv[4];
    if (srcSel == 2) {
        float4 x = *(const float4*)(g_ego3 + (size_t)slot * EMB + t * 4);
        xv[0] = x.x; xv[1] = x.y; xv[2] = x.z; xv[3] = x.w;
    } else {
        uint2 u = *(const uint2*)(g_x16 + (size_t)node * EMB + t * 4);
        float2 lo = __half22float2(*(const __half2*)&u.x);
        float2 hi = __half22float2(*(const __half2*)&u.y);
        xv[0] = lo.x; xv[1] = lo.y; xv[2] = hi.x; xv[3] = hi.y;
    }
    float ss = xv[0] * xv[0] + xv[1] * xv[1] + xv[2] * xv[2] + xv[3] * xv[3];
    #pragma unroll
    for (int o = 16; o; o >>= 1) ss += __shfl_xor_sync(0xffffffffu, ss, o);
    __shared__ float ws[4];
    if ((t & 31) == 0) ws[t >> 5] = ss;
    __syncthreads();
    float tot = ws[0] + ws[1] + ws[2] + ws[3];
    float inv = 1.f / fmaxf(sqrtf(tot), 1e-12f);

    float* o4 = out + (size_t)slot * EMB + t * 4;
    float4 cur = *(float4*)o4;
    cur.x += xv[0] * inv; cur.y += xv[1] * inv;
    cur.z += xv[2] * inv; cur.w += xv[3] * inv;
    *(float4*)o4 = cur;
}

// ---------------- launch ----------------
extern "C" void kernel_launch(void* const* d_in, const int* in_sizes, int n_in,
                              void* d_out, int out_size)
{
    const float* vis   = (const float*)d_in[0];
    const float* txt   = (const float*)d_in[1];
    const int*   er    = (const int*)  d_in[2];
    const int*   ec    = (const int*)  d_in[3];
    const float* ev    = (const float*)d_in[4];
    const int*   items = (const int*)  d_in[5];
    const float* Wgc   = (const float*)d_in[6];
    const float* bgc   = (const float*)d_in[7];
    const float* Wgc2  = (const float*)d_in[8];
    const float* bgc2  = (const float*)d_in[9];
    const float* Wbi   = (const float*)d_in[10];
    const float* bbi   = (const float*)d_in[11];
    float* out = (float*)d_out;
    int nnz = in_sizes[2];

    cudaFuncSetAttribute(k_gemm, cudaFuncAttributeMaxDynamicSharedMemorySize, GEMM_SMEM);

    const int SPMM_B = 2048;
    dim3 gGrid(2, (NNODES + 127) / 128);   // (2, 782)
    dim3 gGrid3(2, NSLOT / 128);           // (2, 64)
    dim3 wGrid(48, 16);

    // init + CSR build + weight conversions
    k_init<<<25000, 256>>>(vis, txt);
    k_zero2<<<782, 256>>>();
    k_hist<<<2048, 256>>>(er, ec, nnz);
    k_scan1<<<SCANB, 256>>>();
    k_scan2<<<1, 1024>>>();
    k_scan3<<<SCANB, 256>>>();
    k_scatter<<<2048, 256>>>(er, ec, ev, nnz);
    k_wtconv<<<wGrid, 256>>>(Wgc, Wgc2, Wbi, 0);
    k_wtconv<<<wGrid, 256>>>(Wgc + 1 * 512 * 512, Wgc2 + 1 * 512 * 512, Wbi + 1 * 512 * 512, 1);
    k_wtconv<<<wGrid, 256>>>(Wgc + 2 * 512 * 512, Wgc2 + 2 * 512 * 512, Wbi + 2 * 512 * 512, 2);

    // acc init
    k_out_init<<<NSLOT, 128>>>(vis, txt, items, out);

    // ---- layer 0: 2-pass spmm, fp16 finals -> gemm -> g_x16 ----
    k_spmm_full<<<SPMM_B, 256>>>(0, 1, 0);
    k_spmm_full<<<SPMM_B, 256>>>(0, 1, 1);
    k_gemm<<<gGrid, 512, GEMM_SMEM>>>(0, 0, bgc, bgc2, bbi, NNODES, nullptr);
    k_norm_acc<<<NSLOT, 128>>>(0, items, out);

    // ---- layer 1 ----
    k_spmm_full<<<SPMM_B, 256>>>(1, 0, 0);
    k_spmm_full<<<SPMM_B, 256>>>(1, 0, 1);
    k_gemm<<<gGrid, 512, GEMM_SMEM>>>(1, 1, bgc + 512, bgc2 + 512, bbi + 512, NNODES, nullptr);
    k_norm_acc<<<NSLOT, 128>>>(1, items, out);

    // ---- layer 2 (subset) ----
    k_spmm_slots<<<1024, 256>>>(items);
    k_gemm<<<gGrid3, 512, GEMM_SMEM>>>(2, 2, bgc + 1024, bgc2 + 1024, bbi + 1024, NSLOT, items);
    k_norm_acc<<<NSLOT, 128>>>(2, items, out);
}